// round 1
// baseline (speedup 1.0000x reference)
#include <cuda_runtime.h>
#include <math.h>

#define NN    64
#define KK    48
#define MM    (NN*KK)      // 3072
#define TOBS  30
#define PREDN 15
#define EMB   64
#define NODE  128
#define EDGE  256
#define ATTD  64
#define CNN   512
#define GT    (4*NODE)     // 512
#define GN    (4*EDGE)     // 1024
#define CONC  (NODE+CNN+EDGE) // 896

// ---------------- persistent device state ----------------
__device__ float d_tht[2][NN*NODE];
__device__ float d_tct[NN*NODE];
__device__ float d_nht[2][MM*EDGE];
__device__ float d_nct[MM*EDGE];
__device__ float d_Ht[NN*EDGE];
__device__ float d_Htacc[NN*EDGE];
__device__ float d_cabs[NN*2], d_crel[NN*2], d_cstep[NN*2];
__device__ float d_nabs[MM*2], d_nstep[MM*2];
__device__ float d_w[MM];      // attention weights
__device__ float d_mf[MM];     // nearby mask as float
__device__ int   d_tmask[NN];
__device__ int   d_gate[2];    // [0]=gate_t, [1]=gate_n
__device__ float d_currN;
// preprocessed weights (gate-interleaved: row r = e*4+q maps orig row q*DIM+e)
__device__ float d_WhhN[GN*EDGE];
__device__ float d_WhhT[GT*NODE];
__device__ float d_WxN[GN*2], d_bN[GN];
__device__ float d_WxT[GT*2], d_bT[GT];
__device__ float d_imgpart[NN*2];

__device__ __forceinline__ float sigm(float x){ return 1.f/(1.f+expf(-x)); }

// ---------------- init: zero state ----------------
__global__ void k_zero(){
    long i0 = (long)blockIdx.x*blockDim.x + threadIdx.x;
    long st = (long)gridDim.x*blockDim.x;
    float* nh = &d_nht[0][0];
    for(long i=i0;i<2L*MM*EDGE;i+=st) nh[i]=0.f;
    for(long i=i0;i<(long)MM*EDGE;i+=st) d_nct[i]=0.f;
    float* th = &d_tht[0][0];
    for(long i=i0;i<2L*NN*NODE;i+=st) th[i]=0.f;
    for(long i=i0;i<(long)NN*NODE;i+=st) d_tct[i]=0.f;
    for(long i=i0;i<(long)NN*EDGE;i+=st){ d_Ht[i]=0.f; d_Htacc[i]=0.f; }
    for(long i=i0;i<(long)MM*2;i+=st){ d_nabs[i]=0.f; d_nstep[i]=0.f; }
    for(long i=i0;i<(long)MM;i+=st){ d_w[i]=0.f; d_mf[i]=0.f; }
    if(i0<NN*2){ d_cabs[i0]=0.f; d_crel[i0]=0.f; d_cstep[i0]=0.f; }
    if(i0<NN) d_tmask[i0]=0;
    if(i0==0){ d_gate[0]=0; d_gate[1]=0; d_currN=0.f; }
}

// ---------------- init: preprocess weights ----------------
__global__ void k_prep(const float* __restrict__ Whh_n, const float* __restrict__ Wih_n,
                       const float* __restrict__ bih_n, const float* __restrict__ bhh_n,
                       const float* __restrict__ Whh_t, const float* __restrict__ Wih_t,
                       const float* __restrict__ bih_t, const float* __restrict__ bhh_t,
                       const float* __restrict__ W_disp, const float* __restrict__ b_disp,
                       const float* __restrict__ img, const float* __restrict__ W_pred){
    int i0 = blockIdx.x*blockDim.x + threadIdx.x;
    int st = gridDim.x*blockDim.x;
    for(int i=i0;i<GN*EDGE;i+=st){
        int r=i/EDGE, k=i%EDGE; int e=r>>2, q=r&3;
        d_WhhN[i] = Whh_n[(q*EDGE+e)*EDGE + k];
    }
    for(int i=i0;i<GT*NODE;i+=st){
        int r=i/NODE, k=i%NODE; int e=r>>2, q=r&3;
        d_WhhT[i] = Whh_t[(q*NODE+e)*NODE + k];
    }
    for(int r=i0;r<GN;r+=st){
        int e=r>>2, q=r&3; int o=q*EDGE+e;
        float w0=0.f,w1=0.f,bb=bih_n[o]+bhh_n[o];
        for(int d=0;d<EMB;d++){
            float wi=Wih_n[o*EMB+d];
            w0+=wi*W_disp[d*2]; w1+=wi*W_disp[d*2+1]; bb+=wi*b_disp[d];
        }
        d_WxN[r*2]=w0; d_WxN[r*2+1]=w1; d_bN[r]=bb;
    }
    for(int r=i0;r<GT;r+=st){
        int e=r>>2, q=r&3; int o=q*NODE+e;
        float w0=0.f,w1=0.f,bb=bih_t[o]+bhh_t[o];
        for(int d=0;d<EMB;d++){
            float wi=Wih_t[o*EMB+d];
            w0+=wi*W_disp[d*2]; w1+=wi*W_disp[d*2+1]; bb+=wi*b_disp[d];
        }
        d_WxT[r*2]=w0; d_WxT[r*2+1]=w1; d_bT[r]=bb;
    }
    for(int i=i0;i<NN*2;i+=st){
        int n=i>>1, j=i&1; float s=0.f;
        for(int c=0;c<CNN;c++) s += img[n*CNN+c]*W_pred[j*CONC + NODE + c];
        d_imgpart[i]=s;
    }
}

// ---------------- per-step small kernel (1 block, 256 threads) ----------------
__global__ void k_small(int t,
    const float* __restrict__ tabs, const float* __restrict__ trel, const float* __restrict__ tstep,
    const float* __restrict__ nabs_in, const float* __restrict__ nstep_in,
    const int* __restrict__ thist, const int* __restrict__ nhist,
    const float* __restrict__ W_att_t, const float* __restrict__ b_att_t,
    const float* __restrict__ W_att_n, const float* __restrict__ b_att_n,
    const float* __restrict__ W_pred, const float* __restrict__ b_pred,
    float* __restrict__ out)
{
    int tid = threadIdx.x;
    __shared__ float s_pred[NN*2];
    __shared__ float s_red[256];
    __shared__ float s_sc[NN][KK];
    __shared__ float s_mx[NN], s_dn[NN];
    __shared__ int s_gate_t, s_currN;

    int cur = (t-1)&1;
    int gate_n_prev = d_gate[1];

    // phase 1: finalize Ht from previous step's accumulation, zero accumulator
    for(int i=tid;i<NN*EDGE;i+=256){
        if(gate_n_prev) d_Ht[i]=d_Htacc[i];
        d_Htacc[i]=0.f;
    }
    __syncthreads();

    bool obs = (t < TOBS);

    // phase 2: pred_out (only needed when !obs)
    if(!obs){
        int item = tid>>1, half = tid&1;   // item = n*2+j
        int n = item>>1, j = item&1;
        float acc = 0.f;
        const float* wp = &W_pred[j*CONC];
        if(half==0){
            const float* th = &d_tht[cur][n*NODE];
            for(int e=0;e<NODE;e++) acc += th[e]*wp[e];
            const float* hh = &d_Ht[n*EDGE];
            for(int e=0;e<64;e++) acc += hh[e]*wp[NODE+CNN+e];
        }else{
            const float* hh = &d_Ht[n*EDGE];
            for(int e=64;e<EDGE;e++) acc += hh[e]*wp[NODE+CNN+e];
        }
        s_red[tid]=acc;
        __syncthreads();
        if(half==0) s_pred[item] = s_red[tid]+s_red[tid+1] + d_imgpart[item] + b_pred[j];
    }
    __syncthreads();

    // phase 3: state updates
    if(obs){
        if(tid<NN*2){
            int n=tid>>1, j=tid&1; int off=(n*TOBS+t)*2+j;
            d_cabs[tid]=tabs[off]; d_crel[tid]=trel[off]; d_cstep[tid]=tstep[off];
        }
        for(int i=tid;i<MM*2;i+=256){
            int m=i>>1, j=i&1; int off=(m*TOBS+t)*2+j;
            d_nabs[i]=nabs_in[off]; d_nstep[i]=nstep_in[off];
        }
    }else{
        if(tid<NN*2){
            float p=s_pred[tid];
            d_cabs[tid]+=p;
            float cr=d_crel[tid]+p; d_crel[tid]=cr;
            d_cstep[tid]=p;
            int n=tid>>1, j=tid&1;
            out[(n*PREDN + (t-TOBS))*2 + j] = cr;
        }
    }
    __syncthreads();

    // phase 4: masks + reductions
    if(tid==0){ s_gate_t=0; s_currN=0; }
    __syncthreads();
    if(obs){
        if(tid<NN){
            int v = (thist[tid] > (TOBS - t)) ? 1 : 0;
            d_tmask[tid]=v;
            if(v) atomicOr(&s_gate_t,1);
        }
        int cnt=0;
        for(int m=tid;m<MM;m+=256){
            int v = (nhist[m] > (TOBS - t)) ? 1 : 0;
            d_mf[m] = v ? 1.f : 0.f;
            cnt += v;
        }
        atomicAdd(&s_currN, cnt);
    }else{
        if(tid<NN) d_tmask[tid]=1;
        for(int m=tid;m<MM;m+=256) d_mf[m]=1.f;
        if(tid==0){ s_gate_t=1; s_currN=MM; }
    }
    __syncthreads();
    if(tid==0){
        int gt = s_gate_t;
        int gn = (gt && s_currN>0) ? 1 : 0;
        d_gate[0]=gt; d_gate[1]=gn; d_currN=(float)s_currN;
    }
    __syncthreads();

    // phase 5: attention weights (an never materialized: sc = dx*P0+dy*P1+P2)
    float currNf = d_currN;
    int n = tid>>2, s = tid&3;
    float crel0=d_crel[n*2], crel1=d_crel[n*2+1];
    float p0=0.f,p1=0.f,p2=0.f;
    for(int a=s*16;a<s*16+16;a++){
        float atv = W_att_t[a*2]*crel0 + W_att_t[a*2+1]*crel1 + b_att_t[a];
        p0 += atv*W_att_n[a*2];
        p1 += atv*W_att_n[a*2+1];
        p2 += atv*b_att_n[a];
    }
    #pragma unroll
    for(int o=1;o<4;o<<=1){
        p0 += __shfl_xor_sync(0xffffffffu,p0,o);
        p1 += __shfl_xor_sync(0xffffffffu,p1,o);
        p2 += __shfl_xor_sync(0xffffffffu,p2,o);
    }
    float cab0=d_cabs[n*2], cab1=d_cabs[n*2+1];
    for(int k=s*12;k<s*12+12;k++){
        int m=n*KK+k;
        float dx=d_nabs[m*2]-cab0, dy=d_nabs[m*2+1]-cab1;
        float sc=(dx*p0+dy*p1+p2)*currNf*0.125f;
        sc *= d_mf[m];
        s_sc[n][k]=sc;
    }
    __syncthreads();
    if(s==0){
        float mx=s_sc[n][0];
        for(int k=1;k<KK;k++) mx=fmaxf(mx,s_sc[n][k]);
        float dn=0.f;
        for(int k=0;k<KK;k++) dn += expf(s_sc[n][k]-mx)*d_mf[n*KK+k];
        s_mx[n]=mx; s_dn[n]=dn+1e-6f;
    }
    __syncthreads();
    for(int k=s*12;k<s*12+12;k++){
        int m=n*KK+k;
        d_w[m] = expf(s_sc[n][k]-s_mx[n])*d_mf[m]/s_dn[n];
    }
}

// ---------------- per-step fused GEMM + LSTM kernel ----------------
// blocks [0,768): nearby  — C(3072 x 1024) = nht @ WhhN^T, gate-interleaved cols
// blocks [768,776): target — C(64 x 512)   = tht @ WhhT^T
// BM=64, BN=64, BK=16, 256 threads, 4x4 per thread (thread owns 4 rows x 1 cell's 4 gates)
__global__ void __launch_bounds__(256) k_lstm(int t)
{
    __shared__ float As[16][68];
    __shared__ float Bs[16][68];
    int cur=(t-1)&1, nxt=t&1;
    int bx = blockIdx.x;
    int tid = threadIdx.x, tx = tid&15, ty = tid>>4;
    float acc[4][4];
    #pragma unroll
    for(int i=0;i<4;i++)
        #pragma unroll
        for(int j=0;j<4;j++) acc[i][j]=0.f;

    if(bx < 768){
        int rowTile = bx % 48, colTile = bx / 48;
        int m0 = rowTile*64, g0 = colTile*64, e0 = colTile*16;
        const float* A = d_nht[cur];
        int r = tid>>2, kkq = (tid&3)*4;
        for(int kt=0; kt<EDGE; kt+=16){
            float4 av = *(const float4*)&A[(m0+r)*EDGE + kt + kkq];
            As[kkq+0][r]=av.x; As[kkq+1][r]=av.y; As[kkq+2][r]=av.z; As[kkq+3][r]=av.w;
            float4 bv = *(const float4*)&d_WhhN[(g0+r)*EDGE + kt + kkq];
            Bs[kkq+0][r]=bv.x; Bs[kkq+1][r]=bv.y; Bs[kkq+2][r]=bv.z; Bs[kkq+3][r]=bv.w;
            __syncthreads();
            #pragma unroll
            for(int k=0;k<16;k++){
                float a0=As[k][ty*4+0],a1=As[k][ty*4+1],a2=As[k][ty*4+2],a3=As[k][ty*4+3];
                float b0=Bs[k][tx*4+0],b1=Bs[k][tx*4+1],b2=Bs[k][tx*4+2],b3=Bs[k][tx*4+3];
                acc[0][0]+=a0*b0; acc[0][1]+=a0*b1; acc[0][2]+=a0*b2; acc[0][3]+=a0*b3;
                acc[1][0]+=a1*b0; acc[1][1]+=a1*b1; acc[1][2]+=a1*b2; acc[1][3]+=a1*b3;
                acc[2][0]+=a2*b0; acc[2][1]+=a2*b1; acc[2][2]+=a2*b2; acc[2][3]+=a2*b3;
                acc[3][0]+=a3*b0; acc[3][1]+=a3*b1; acc[3][2]+=a3*b2; acc[3][3]+=a3*b3;
            }
            __syncthreads();
        }
        int gate_n = d_gate[1];
        int e = e0 + tx;
        #pragma unroll
        for(int i=0;i<4;i++){
            int m = m0 + ty*4 + i;
            float x0=d_nstep[m*2], x1=d_nstep[m*2+1];
            float g4[4];
            #pragma unroll
            for(int q=0;q<4;q++){
                int rr = g0 + tx*4 + q;
                g4[q] = acc[i][q] + x0*d_WxN[rr*2] + x1*d_WxN[rr*2+1] + d_bN[rr];
            }
            float ig=sigm(g4[0]), fg=sigm(g4[1]), gg=tanhf(g4[2]), og=sigm(g4[3]);
            float cold = d_nct[m*EDGE+e];
            float c2 = fg*cold + ig*gg;
            float h2 = og*tanhf(c2);
            bool un = gate_n && (d_mf[m] > 0.f);
            float hv;
            if(un){ d_nct[m*EDGE+e]=c2; hv=h2; }
            else  { hv = d_nht[cur][m*EDGE+e]; }
            d_nht[nxt][m*EDGE+e]=hv;
            if(gate_n){
                float wv = d_w[m];
                if(wv != 0.f) atomicAdd(&d_Htacc[(m/KK)*EDGE+e], wv*hv);
            }
        }
    }else{
        int colTile = bx - 768;
        int g0 = colTile*64, e0 = colTile*16;
        const float* A = d_tht[cur];
        int r = tid>>2, kkq = (tid&3)*4;
        for(int kt=0; kt<NODE; kt+=16){
            float4 av = *(const float4*)&A[r*NODE + kt + kkq];
            As[kkq+0][r]=av.x; As[kkq+1][r]=av.y; As[kkq+2][r]=av.z; As[kkq+3][r]=av.w;
            float4 bv = *(const float4*)&d_WhhT[(g0+r)*NODE + kt + kkq];
            Bs[kkq+0][r]=bv.x; Bs[kkq+1][r]=bv.y; Bs[kkq+2][r]=bv.z; Bs[kkq+3][r]=bv.w;
            __syncthreads();
            #pragma unroll
            for(int k=0;k<16;k++){
                float a0=As[k][ty*4+0],a1=As[k][ty*4+1],a2=As[k][ty*4+2],a3=As[k][ty*4+3];
                float b0=Bs[k][tx*4+0],b1=Bs[k][tx*4+1],b2=Bs[k][tx*4+2],b3=Bs[k][tx*4+3];
                acc[0][0]+=a0*b0; acc[0][1]+=a0*b1; acc[0][2]+=a0*b2; acc[0][3]+=a0*b3;
                acc[1][0]+=a1*b0; acc[1][1]+=a1*b1; acc[1][2]+=a1*b2; acc[1][3]+=a1*b3;
                acc[2][0]+=a2*b0; acc[2][1]+=a2*b1; acc[2][2]+=a2*b2; acc[2][3]+=a2*b3;
                acc[3][0]+=a3*b0; acc[3][1]+=a3*b1; acc[3][2]+=a3*b2; acc[3][3]+=a3*b3;
            }
            __syncthreads();
        }
        int gate_t = d_gate[0];
        int e = e0 + tx;
        #pragma unroll
        for(int i=0;i<4;i++){
            int n = ty*4 + i;
            float x0=d_cstep[n*2], x1=d_cstep[n*2+1];
            float g4[4];
            #pragma unroll
            for(int q=0;q<4;q++){
                int rr = g0 + tx*4 + q;
                g4[q] = acc[i][q] + x0*d_WxT[rr*2] + x1*d_WxT[rr*2+1] + d_bT[rr];
            }
            float ig=sigm(g4[0]), fg=sigm(g4[1]), gg=tanhf(g4[2]), og=sigm(g4[3]);
            float cold = d_tct[n*NODE+e];
            float c2 = fg*cold + ig*gg;
            float h2 = og*tanhf(c2);
            bool un = gate_t && d_tmask[n];
            float hv;
            if(un){ d_tct[n*NODE+e]=c2; hv=h2; }
            else  { hv = d_tht[cur][n*NODE+e]; }
            d_tht[nxt][n*NODE+e]=hv;
        }
    }
}

// ---------------- launch ----------------
extern "C" void kernel_launch(void* const* d_in, const int* in_sizes, int n_in,
                              void* d_out, int out_size)
{
    const float* img    = (const float*)d_in[0];
    const float* tabs   = (const float*)d_in[1];
    const float* trel   = (const float*)d_in[2];
    const float* tstep  = (const float*)d_in[3];
    const float* nabs   = (const float*)d_in[4];
    // d_in[5] = nearby_obs_pos_rel (unused by reference step)
    const float* nstep  = (const float*)d_in[6];
    const int*   thist  = (const int*)d_in[7];
    const int*   nhist  = (const int*)d_in[8];
    const float* W_disp = (const float*)d_in[9];
    const float* b_disp = (const float*)d_in[10];
    const float* Wih_t  = (const float*)d_in[11];
    const float* Whh_t  = (const float*)d_in[12];
    const float* bih_t  = (const float*)d_in[13];
    const float* bhh_t  = (const float*)d_in[14];
    const float* Wih_n  = (const float*)d_in[15];
    const float* Whh_n  = (const float*)d_in[16];
    const float* bih_n  = (const float*)d_in[17];
    const float* bhh_n  = (const float*)d_in[18];
    const float* W_att_t= (const float*)d_in[19];
    const float* b_att_t= (const float*)d_in[20];
    const float* W_att_n= (const float*)d_in[21];
    const float* b_att_n= (const float*)d_in[22];
    const float* W_pred = (const float*)d_in[23];
    const float* b_pred = (const float*)d_in[24];
    float* out = (float*)d_out;

    k_zero<<<256,256>>>();
    k_prep<<<256,256>>>(Whh_n,Wih_n,bih_n,bhh_n,Whh_t,Wih_t,bih_t,bhh_t,
                        W_disp,b_disp,img,W_pred);
    for(int t=1; t<TOBS+PREDN; t++){
        k_small<<<1,256>>>(t,tabs,trel,tstep,nabs,nstep,thist,nhist,
                           W_att_t,b_att_t,W_att_n,b_att_n,W_pred,b_pred,out);
        k_lstm<<<776,256>>>(t);
    }
}

// round 2
// speedup vs baseline: 1.2598x; 1.2598x over previous
#include <cuda_runtime.h>
#include <math.h>

#define NN    64
#define KK    48
#define MM    (NN*KK)      // 3072
#define TOBS  30
#define PREDN 15
#define TSTEPS (TOBS+PREDN)  // 45, t runs 1..44
#define EMB   64
#define NODE  128
#define EDGE  256
#define ATTD  64
#define CNN   512
#define GT    (4*NODE)     // 512
#define GN    (4*EDGE)     // 1024
#define CONC  (NODE+CNN+EDGE) // 896

// ---------------- persistent device state ----------------
__device__ float d_tht[2][NN*NODE];
__device__ float d_tct[NN*NODE];
__device__ float d_nht[2][MM*EDGE];
__device__ float d_nct[MM*EDGE];
__device__ float d_Ht[NN*EDGE];
__device__ float d_Htacc[NN*EDGE];
__device__ float d_cabs[NN*2], d_crel[NN*2], d_cstep[NN*2];
__device__ float d_w[MM];      // attention weights
// per-step gate tables
__device__ int   d_gateTt[TSTEPS];
__device__ int   d_gateNt[TSTEPS];
__device__ float d_currNt[TSTEPS];
// preprocessed weights (gate-interleaved: row r = e*4+q maps orig row q*DIM+e)
__device__ float d_WhhN[GN*EDGE];
__device__ float d_WhhT[GT*NODE];
__device__ float d_WxN[GN*2], d_bN[GN];
__device__ float d_WxT[GT*2], d_bT[GT];
__device__ float d_imgpart[NN*2];

__device__ __forceinline__ float sigm(float x){ return 1.f/(1.f+expf(-x)); }

// ---------------- init: zero state ----------------
__global__ void k_zero(){
    long i0 = (long)blockIdx.x*blockDim.x + threadIdx.x;
    long st = (long)gridDim.x*blockDim.x;
    float* nh = &d_nht[0][0];
    for(long i=i0;i<2L*MM*EDGE;i+=st) nh[i]=0.f;
    for(long i=i0;i<(long)MM*EDGE;i+=st) d_nct[i]=0.f;
    float* th = &d_tht[0][0];
    for(long i=i0;i<2L*NN*NODE;i+=st) th[i]=0.f;
    for(long i=i0;i<(long)NN*NODE;i+=st) d_tct[i]=0.f;
    for(long i=i0;i<(long)NN*EDGE;i+=st){ d_Ht[i]=0.f; d_Htacc[i]=0.f; }
    if(i0<NN*2){ d_cabs[i0]=0.f; d_crel[i0]=0.f; d_cstep[i0]=0.f; }
}

// ---------------- init: per-step gate tables ----------------
__global__ void k_tables(const int* __restrict__ thist, const int* __restrict__ nhist){
    int t = blockIdx.x + 1;             // 1..44
    int tid = threadIdx.x;
    __shared__ int s_cnt[256];
    __shared__ int s_any[256];
    int cnt=0, any=0;
    if(t < TOBS){
        for(int m=tid;m<MM;m+=256) cnt += (nhist[m] > (TOBS - t)) ? 1 : 0;
        for(int n=tid;n<NN;n+=256) any |= (thist[n] > (TOBS - t)) ? 1 : 0;
    }else{
        cnt = (tid==0)?MM:0; any = 1;
    }
    s_cnt[tid]=cnt; s_any[tid]=any;
    __syncthreads();
    for(int o=128;o>0;o>>=1){
        if(tid<o){ s_cnt[tid]+=s_cnt[tid+o]; s_any[tid]|=s_any[tid+o]; }
        __syncthreads();
    }
    if(tid==0){
        int gt = s_any[0]?1:0;
        int cn = s_cnt[0];
        int gn = (gt && cn>0)?1:0;
        d_gateTt[t]=gt; d_gateNt[t]=gn; d_currNt[t]=(float)cn;
    }
}

// ---------------- init: preprocess weights ----------------
__global__ void k_prep(const float* __restrict__ Whh_n, const float* __restrict__ Wih_n,
                       const float* __restrict__ bih_n, const float* __restrict__ bhh_n,
                       const float* __restrict__ Whh_t, const float* __restrict__ Wih_t,
                       const float* __restrict__ bih_t, const float* __restrict__ bhh_t,
                       const float* __restrict__ W_disp, const float* __restrict__ b_disp,
                       const float* __restrict__ img, const float* __restrict__ W_pred){
    int i0 = blockIdx.x*blockDim.x + threadIdx.x;
    int st = gridDim.x*blockDim.x;
    for(int i=i0;i<GN*EDGE;i+=st){
        int r=i/EDGE, k=i%EDGE; int e=r>>2, q=r&3;
        d_WhhN[i] = Whh_n[(q*EDGE+e)*EDGE + k];
    }
    for(int i=i0;i<GT*NODE;i+=st){
        int r=i/NODE, k=i%NODE; int e=r>>2, q=r&3;
        d_WhhT[i] = Whh_t[(q*NODE+e)*NODE + k];
    }
    for(int r=i0;r<GN;r+=st){
        int e=r>>2, q=r&3; int o=q*EDGE+e;
        float w0=0.f,w1=0.f,bb=bih_n[o]+bhh_n[o];
        for(int d=0;d<EMB;d++){
            float wi=Wih_n[o*EMB+d];
            w0+=wi*W_disp[d*2]; w1+=wi*W_disp[d*2+1]; bb+=wi*b_disp[d];
        }
        d_WxN[r*2]=w0; d_WxN[r*2+1]=w1; d_bN[r]=bb;
    }
    for(int r=i0;r<GT;r+=st){
        int e=r>>2, q=r&3; int o=q*NODE+e;
        float w0=0.f,w1=0.f,bb=bih_t[o]+bhh_t[o];
        for(int d=0;d<EMB;d++){
            float wi=Wih_t[o*EMB+d];
            w0+=wi*W_disp[d*2]; w1+=wi*W_disp[d*2+1]; bb+=wi*b_disp[d];
        }
        d_WxT[r*2]=w0; d_WxT[r*2+1]=w1; d_bT[r]=bb;
    }
    for(int i=i0;i<NN*2;i+=st){
        int n=i>>1, j=i&1; float s=0.f;
        for(int c=0;c<CNN;c++) s += img[n*CNN+c]*W_pred[j*CONC + NODE + c];
        d_imgpart[i]=s;
    }
}

// ---------------- per-step small kernel (1 block, 1024 threads) ----------------
__global__ void __launch_bounds__(1024) k_small(int t,
    const float* __restrict__ tabs, const float* __restrict__ trel, const float* __restrict__ tstep,
    const float* __restrict__ nabs_in,
    const int* __restrict__ nhist,
    const float* __restrict__ W_att_t, const float* __restrict__ b_att_t,
    const float* __restrict__ W_att_n, const float* __restrict__ b_att_n,
    const float* __restrict__ W_pred, const float* __restrict__ b_pred,
    float* __restrict__ out)
{
    int tid = threadIdx.x;
    __shared__ float s_pred[NN*2];

    int cur = (t-1)&1;
    int gate_n_prev = (t>=2) ? d_gateNt[t-1] : 0;
    bool obs = (t < TOBS);
    int tc = obs ? t : (TOBS-1);

    // phase 1: finalize Ht from previous step's accumulation, zero accumulator
    for(int i=tid;i<NN*EDGE;i+=1024){
        if(gate_n_prev) d_Ht[i]=d_Htacc[i];
        d_Htacc[i]=0.f;
    }
    __syncthreads();

    // phase 2: pred_out (only needed when !obs). 8 threads per (n,j) item.
    if(!obs){
        int item = tid>>3, sub = tid&7;   // item = n*2+j  (0..127)
        int n = item>>1, j = item&1;
        const float* wp = &W_pred[j*CONC];
        const float* th = &d_tht[cur][n*NODE];
        const float* hh = &d_Ht[n*EDGE];
        float acc = 0.f;
        for(int e=sub*16;e<sub*16+16;e++) acc += th[e]*wp[e];
        for(int e=sub*32;e<sub*32+32;e++) acc += hh[e]*wp[NODE+CNN+e];
        #pragma unroll
        for(int o=1;o<8;o<<=1) acc += __shfl_xor_sync(0xffffffffu, acc, o);
        if(sub==0) s_pred[item] = acc + d_imgpart[item] + b_pred[j];
    }
    __syncthreads();

    // phase 3: target state updates
    if(obs){
        if(tid<NN*2){
            int n=tid>>1, j=tid&1; int off=(n*TOBS+t)*2+j;
            d_cabs[tid]=tabs[off]; d_crel[tid]=trel[off]; d_cstep[tid]=tstep[off];
        }
    }else{
        if(tid<NN*2){
            float p=s_pred[tid];
            d_cabs[tid]+=p;
            float cr=d_crel[tid]+p; d_crel[tid]=cr;
            d_cstep[tid]=p;
            int n=tid>>1, j=tid&1;
            out[(n*PREDN + (t-TOBS))*2 + j] = cr;
        }
    }
    __syncthreads();

    // phase 4: attention weights. 16 threads per n.
    float currNf = d_currNt[t];
    int n = tid>>4, s = tid&15;
    float crel0=d_crel[n*2], crel1=d_crel[n*2+1];
    float p0=0.f,p1=0.f,p2=0.f;
    for(int a=s*4;a<s*4+4;a++){
        float atv = W_att_t[a*2]*crel0 + W_att_t[a*2+1]*crel1 + b_att_t[a];
        p0 += atv*W_att_n[a*2];
        p1 += atv*W_att_n[a*2+1];
        p2 += atv*b_att_n[a];
    }
    #pragma unroll
    for(int o=1;o<16;o<<=1){
        p0 += __shfl_xor_sync(0xffffffffu,p0,o);
        p1 += __shfl_xor_sync(0xffffffffu,p1,o);
        p2 += __shfl_xor_sync(0xffffffffu,p2,o);
    }
    float cab0=d_cabs[n*2], cab1=d_cabs[n*2+1];
    float sc[3], mf[3];
    #pragma unroll
    for(int kk=0;kk<3;kk++){
        int k = s*3+kk;
        int m = n*KK+k;
        int off = (m*TOBS+tc)*2;
        float dx=nabs_in[off]-cab0, dy=nabs_in[off+1]-cab1;
        float mv = obs ? ((nhist[m] > (TOBS - t)) ? 1.f : 0.f) : 1.f;
        mf[kk]=mv;
        sc[kk]=(dx*p0+dy*p1+p2)*currNf*0.125f*mv;
    }
    float mx = fmaxf(sc[0],fmaxf(sc[1],sc[2]));
    #pragma unroll
    for(int o=1;o<16;o<<=1) mx = fmaxf(mx, __shfl_xor_sync(0xffffffffu,mx,o));
    float dn = expf(sc[0]-mx)*mf[0]+expf(sc[1]-mx)*mf[1]+expf(sc[2]-mx)*mf[2];
    #pragma unroll
    for(int o=1;o<16;o<<=1) dn += __shfl_xor_sync(0xffffffffu,dn,o);
    dn += 1e-6f;
    #pragma unroll
    for(int kk=0;kk<3;kk++){
        int m = n*KK + s*3+kk;
        d_w[m] = expf(sc[kk]-mx)*mf[kk]/dn;
    }
}

// ---------------- per-step fused GEMM + LSTM kernel ----------------
// blocks [0,768): nearby  — C(3072 x 1024) = nht @ WhhN^T, gate-interleaved cols
// blocks [768,776): target — C(64 x 512)   = tht @ WhhT^T
// BM=64, BN=64, BK=16, 256 threads, 4x4 per thread (thread owns 4 rows x 1 cell's 4 gates)
__global__ void __launch_bounds__(256) k_lstm(int t,
    const float* __restrict__ nstep_in, const int* __restrict__ nhist,
    const int* __restrict__ thist)
{
    __shared__ float As[16][68];   // row stride 272B -> 16B aligned slices
    __shared__ float Bs[16][68];
    int cur=(t-1)&1, nxt=t&1;
    bool obs = (t < TOBS);
    int tc = obs ? t : (TOBS-1);
    int bx = blockIdx.x;
    int tid = threadIdx.x, tx = tid&15, ty = tid>>4;
    float acc[4][4];
    #pragma unroll
    for(int i=0;i<4;i++)
        #pragma unroll
        for(int j=0;j<4;j++) acc[i][j]=0.f;

    if(bx < 768){
        int rowTile = bx % 48, colTile = bx / 48;
        int m0 = rowTile*64, g0 = colTile*64, e0 = colTile*16;
        const float* A = d_nht[cur];
        int r = tid>>2, kkq = (tid&3)*4;
        for(int kt=0; kt<EDGE; kt+=16){
            float4 av = *(const float4*)&A[(m0+r)*EDGE + kt + kkq];
            As[kkq+0][r]=av.x; As[kkq+1][r]=av.y; As[kkq+2][r]=av.z; As[kkq+3][r]=av.w;
            float4 bv = *(const float4*)&d_WhhN[(g0+r)*EDGE + kt + kkq];
            Bs[kkq+0][r]=bv.x; Bs[kkq+1][r]=bv.y; Bs[kkq+2][r]=bv.z; Bs[kkq+3][r]=bv.w;
            __syncthreads();
            #pragma unroll
            for(int k=0;k<16;k++){
                float4 a = *(const float4*)&As[k][ty*4];
                float4 b = *(const float4*)&Bs[k][tx*4];
                acc[0][0]+=a.x*b.x; acc[0][1]+=a.x*b.y; acc[0][2]+=a.x*b.z; acc[0][3]+=a.x*b.w;
                acc[1][0]+=a.y*b.x; acc[1][1]+=a.y*b.y; acc[1][2]+=a.y*b.z; acc[1][3]+=a.y*b.w;
                acc[2][0]+=a.z*b.x; acc[2][1]+=a.z*b.y; acc[2][2]+=a.z*b.z; acc[2][3]+=a.z*b.w;
                acc[3][0]+=a.w*b.x; acc[3][1]+=a.w*b.y; acc[3][2]+=a.w*b.z; acc[3][3]+=a.w*b.w;
            }
            __syncthreads();
        }
        int gate_n = d_gateNt[t];
        int e = e0 + tx;
        #pragma unroll
        for(int i=0;i<4;i++){
            int m = m0 + ty*4 + i;
            int off = (m*TOBS+tc)*2;
            float x0=nstep_in[off], x1=nstep_in[off+1];
            float g4[4];
            #pragma unroll
            for(int q=0;q<4;q++){
                int rr = g0 + tx*4 + q;
                g4[q] = acc[i][q] + x0*d_WxN[rr*2] + x1*d_WxN[rr*2+1] + d_bN[rr];
            }
            float ig=sigm(g4[0]), fg=sigm(g4[1]), gg=tanhf(g4[2]), og=sigm(g4[3]);
            float cold = d_nct[m*EDGE+e];
            float c2 = fg*cold + ig*gg;
            float h2 = og*tanhf(c2);
            bool mv = obs ? (nhist[m] > (TOBS - t)) : true;
            bool un = gate_n && mv;
            float hv;
            if(un){ d_nct[m*EDGE+e]=c2; hv=h2; }
            else  { hv = d_nht[cur][m*EDGE+e]; }
            d_nht[nxt][m*EDGE+e]=hv;
            if(gate_n){
                float wv = d_w[m];
                if(wv != 0.f) atomicAdd(&d_Htacc[(m/KK)*EDGE+e], wv*hv);
            }
        }
    }else{
        int colTile = bx - 768;
        int g0 = colTile*64, e0 = colTile*16;
        const float* A = d_tht[cur];
        int r = tid>>2, kkq = (tid&3)*4;
        for(int kt=0; kt<NODE; kt+=16){
            float4 av = *(const float4*)&A[r*NODE + kt + kkq];
            As[kkq+0][r]=av.x; As[kkq+1][r]=av.y; As[kkq+2][r]=av.z; As[kkq+3][r]=av.w;
            float4 bv = *(const float4*)&d_WhhT[(g0+r)*NODE + kt + kkq];
            Bs[kkq+0][r]=bv.x; Bs[kkq+1][r]=bv.y; Bs[kkq+2][r]=bv.z; Bs[kkq+3][r]=bv.w;
            __syncthreads();
            #pragma unroll
            for(int k=0;k<16;k++){
                float4 a = *(const float4*)&As[k][ty*4];
                float4 b = *(const float4*)&Bs[k][tx*4];
                acc[0][0]+=a.x*b.x; acc[0][1]+=a.x*b.y; acc[0][2]+=a.x*b.z; acc[0][3]+=a.x*b.w;
                acc[1][0]+=a.y*b.x; acc[1][1]+=a.y*b.y; acc[1][2]+=a.y*b.z; acc[1][3]+=a.y*b.w;
                acc[2][0]+=a.z*b.x; acc[2][1]+=a.z*b.y; acc[2][2]+=a.z*b.z; acc[2][3]+=a.z*b.w;
                acc[3][0]+=a.w*b.x; acc[3][1]+=a.w*b.y; acc[3][2]+=a.w*b.z; acc[3][3]+=a.w*b.w;
            }
            __syncthreads();
        }
        int gate_t = d_gateTt[t];
        int e = e0 + tx;
        #pragma unroll
        for(int i=0;i<4;i++){
            int n = ty*4 + i;
            float x0=d_cstep[n*2], x1=d_cstep[n*2+1];
            float g4[4];
            #pragma unroll
            for(int q=0;q<4;q++){
                int rr = g0 + tx*4 + q;
                g4[q] = acc[i][q] + x0*d_WxT[rr*2] + x1*d_WxT[rr*2+1] + d_bT[rr];
            }
            float ig=sigm(g4[0]), fg=sigm(g4[1]), gg=tanhf(g4[2]), og=sigm(g4[3]);
            float cold = d_tct[n*NODE+e];
            float c2 = fg*cold + ig*gg;
            float h2 = og*tanhf(c2);
            bool tm = obs ? (thist[n] > (TOBS - t)) : true;
            bool un = gate_t && tm;
            float hv;
            if(un){ d_tct[n*NODE+e]=c2; hv=h2; }
            else  { hv = d_tht[cur][n*NODE+e]; }
            d_tht[nxt][n*NODE+e]=hv;
        }
    }
}

// ---------------- launch ----------------
extern "C" void kernel_launch(void* const* d_in, const int* in_sizes, int n_in,
                              void* d_out, int out_size)
{
    const float* img    = (const float*)d_in[0];
    const float* tabs   = (const float*)d_in[1];
    const float* trel   = (const float*)d_in[2];
    const float* tstep  = (const float*)d_in[3];
    const float* nabs   = (const float*)d_in[4];
    // d_in[5] = nearby_obs_pos_rel (unused by reference step)
    const float* nstep  = (const float*)d_in[6];
    const int*   thist  = (const int*)d_in[7];
    const int*   nhist  = (const int*)d_in[8];
    const float* W_disp = (const float*)d_in[9];
    const float* b_disp = (const float*)d_in[10];
    const float* Wih_t  = (const float*)d_in[11];
    const float* Whh_t  = (const float*)d_in[12];
    const float* bih_t  = (const float*)d_in[13];
    const float* bhh_t  = (const float*)d_in[14];
    const float* Wih_n  = (const float*)d_in[15];
    const float* Whh_n  = (const float*)d_in[16];
    const float* bih_n  = (const float*)d_in[17];
    const float* bhh_n  = (const float*)d_in[18];
    const float* W_att_t= (const float*)d_in[19];
    const float* b_att_t= (const float*)d_in[20];
    const float* W_att_n= (const float*)d_in[21];
    const float* b_att_n= (const float*)d_in[22];
    const float* W_pred = (const float*)d_in[23];
    const float* b_pred = (const float*)d_in[24];
    float* out = (float*)d_out;

    k_zero<<<256,256>>>();
    k_tables<<<TSTEPS-1,256>>>(thist,nhist);
    k_prep<<<256,256>>>(Whh_n,Wih_n,bih_n,bhh_n,Whh_t,Wih_t,bih_t,bhh_t,
                        W_disp,b_disp,img,W_pred);
    for(int t=1; t<TSTEPS; t++){
        k_small<<<1,1024>>>(t,tabs,trel,tstep,nabs,nhist,
                            W_att_t,b_att_t,W_att_n,b_att_n,W_pred,b_pred,out);
        k_lstm<<<776,256>>>(t,nstep,nhist,thist);
    }
}

// round 3
// speedup vs baseline: 1.6622x; 1.3194x over previous
#include <cuda_runtime.h>
#include <math.h>

#define NN    64
#define KK    48
#define MM    (NN*KK)      // 3072
#define TOBS  30
#define PREDN 15
#define TSTEPS (TOBS+PREDN)  // 45, t runs 1..44
#define EMB   64
#define NODE  128
#define EDGE  256
#define ATTD  64
#define CNN   512
#define GT    (4*NODE)     // 512
#define GN    (4*EDGE)     // 1024
#define CONC  (NODE+CNN+EDGE) // 896

typedef unsigned long long ULL;

// f32x2 packed math (bitwise == 2x scalar fp32 fma)
#define PK(d,s)   asm("mov.b64 %0, {%1, %1};" : "=l"(d) : "f"(s))
#define UPK(lo,hi,p) asm("mov.b64 {%0, %1}, %2;" : "=f"(lo), "=f"(hi) : "l"(p))
#define FMA2(c,a,b) asm("fma.rn.f32x2 %0, %1, %2, %0;" : "+l"(c) : "l"(a), "l"(b))

// ---------------- persistent device state ----------------
// transposed layouts: nhtT[e][m], thtT[e][n]
__device__ float d_thtT[2][NODE*NN];
__device__ float d_tct[NN*NODE];
__device__ float d_nhtT[2][EDGE*MM];
__device__ float d_nct[MM*EDGE];
__device__ float d_Ht[NN*EDGE];
__device__ float d_Htacc[NN*EDGE];
__device__ float d_cabs[NN*2], d_crel[NN*2], d_cstep[NN*2];
__device__ float d_w[MM];      // attention weights
__device__ int   d_flag;       // step publish flag
// per-step gate tables
__device__ int   d_gateTt[TSTEPS];
__device__ int   d_gateNt[TSTEPS];
__device__ float d_currNt[TSTEPS];
// preprocessed weights, transposed + gate-interleaved: col g = e*4+q
__device__ float d_WhhNT[EDGE*GN];   // [k][g]
__device__ float d_WhhTT[NODE*GT];   // [k][g]
__device__ float d_WxN[GN*2], d_bN[GN];
__device__ float d_WxT[GT*2], d_bT[GT];
__device__ float d_imgpart[NN*2];

__device__ __forceinline__ float sigm(float x){ return 1.f/(1.f+expf(-x)); }

// ---------------- init: zero state ----------------
__global__ void k_zero(){
    long i0 = (long)blockIdx.x*blockDim.x + threadIdx.x;
    long st = (long)gridDim.x*blockDim.x;
    float* nh = &d_nhtT[0][0];
    for(long i=i0;i<2L*MM*EDGE;i+=st) nh[i]=0.f;
    for(long i=i0;i<(long)MM*EDGE;i+=st) d_nct[i]=0.f;
    float* th = &d_thtT[0][0];
    for(long i=i0;i<2L*NN*NODE;i+=st) th[i]=0.f;
    for(long i=i0;i<(long)NN*NODE;i+=st) d_tct[i]=0.f;
    for(long i=i0;i<(long)NN*EDGE;i+=st){ d_Ht[i]=0.f; d_Htacc[i]=0.f; }
    if(i0<NN*2){ d_cabs[i0]=0.f; d_crel[i0]=0.f; d_cstep[i0]=0.f; }
    if(i0==0) d_flag=0;
}

// ---------------- init: per-step gate tables ----------------
__global__ void k_tables(const int* __restrict__ thist, const int* __restrict__ nhist){
    int t = blockIdx.x + 1;             // 1..44
    int tid = threadIdx.x;
    __shared__ int s_cnt[256];
    __shared__ int s_any[256];
    int cnt=0, any=0;
    if(t < TOBS){
        for(int m=tid;m<MM;m+=256) cnt += (nhist[m] > (TOBS - t)) ? 1 : 0;
        for(int n=tid;n<NN;n+=256) any |= (thist[n] > (TOBS - t)) ? 1 : 0;
    }else{
        cnt = (tid==0)?MM:0; any = 1;
    }
    s_cnt[tid]=cnt; s_any[tid]=any;
    __syncthreads();
    for(int o=128;o>0;o>>=1){
        if(tid<o){ s_cnt[tid]+=s_cnt[tid+o]; s_any[tid]|=s_any[tid+o]; }
        __syncthreads();
    }
    if(tid==0){
        int gt = s_any[0]?1:0;
        int cn = s_cnt[0];
        int gn = (gt && cn>0)?1:0;
        d_gateTt[t]=gt; d_gateNt[t]=gn; d_currNt[t]=(float)cn;
    }
}

// ---------------- init: preprocess weights ----------------
__global__ void k_prep(const float* __restrict__ Whh_n, const float* __restrict__ Wih_n,
                       const float* __restrict__ bih_n, const float* __restrict__ bhh_n,
                       const float* __restrict__ Whh_t, const float* __restrict__ Wih_t,
                       const float* __restrict__ bih_t, const float* __restrict__ bhh_t,
                       const float* __restrict__ W_disp, const float* __restrict__ b_disp,
                       const float* __restrict__ img, const float* __restrict__ W_pred){
    int i0 = blockIdx.x*blockDim.x + threadIdx.x;
    int st = gridDim.x*blockDim.x;
    // transposed + gate-interleaved: d_WhhNT[k*GN + g], g=e*4+q
    for(int i=i0;i<EDGE*GN;i+=st){
        int k=i/GN, g=i%GN; int e=g>>2, q=g&3;
        d_WhhNT[i] = Whh_n[(q*EDGE+e)*EDGE + k];
    }
    for(int i=i0;i<NODE*GT;i+=st){
        int k=i/GT, g=i%GT; int e=g>>2, q=g&3;
        d_WhhTT[i] = Whh_t[(q*NODE+e)*NODE + k];
    }
    for(int r=i0;r<GN;r+=st){
        int e=r>>2, q=r&3; int o=q*EDGE+e;
        float w0=0.f,w1=0.f,bb=bih_n[o]+bhh_n[o];
        for(int d=0;d<EMB;d++){
            float wi=Wih_n[o*EMB+d];
            w0+=wi*W_disp[d*2]; w1+=wi*W_disp[d*2+1]; bb+=wi*b_disp[d];
        }
        d_WxN[r*2]=w0; d_WxN[r*2+1]=w1; d_bN[r]=bb;
    }
    for(int r=i0;r<GT;r+=st){
        int e=r>>2, q=r&3; int o=q*NODE+e;
        float w0=0.f,w1=0.f,bb=bih_t[o]+bhh_t[o];
        for(int d=0;d<EMB;d++){
            float wi=Wih_t[o*EMB+d];
            w0+=wi*W_disp[d*2]; w1+=wi*W_disp[d*2+1]; bb+=wi*b_disp[d];
        }
        d_WxT[r*2]=w0; d_WxT[r*2+1]=w1; d_bT[r]=bb;
    }
    for(int i=i0;i<NN*2;i+=st){
        int n=i>>1, j=i&1; float s=0.f;
        for(int c=0;c<CNN;c++) s += img[n*CNN+c]*W_pred[j*CONC + NODE + c];
        d_imgpart[i]=s;
    }
}

// =========================================================================
// the per-step kernel: block 0 does the "small" serial work and publishes
// d_flag=t; blocks 1..192 do nearby GEMM+LSTM; blocks 193..196 target.
// =========================================================================
__global__ void __launch_bounds__(256,2) k_step(int t,
    const float* __restrict__ tabs, const float* __restrict__ trel, const float* __restrict__ tstep,
    const float* __restrict__ nabs_in, const float* __restrict__ nstep_in,
    const int* __restrict__ thist, const int* __restrict__ nhist,
    const float* __restrict__ W_att_t, const float* __restrict__ b_att_t,
    const float* __restrict__ W_att_n, const float* __restrict__ b_att_n,
    const float* __restrict__ W_pred, const float* __restrict__ b_pred,
    float* __restrict__ out)
{
    __shared__ __align__(16) float As[32][128];
    __shared__ __align__(16) float Bs[32][140];   // physical col p(c)=c+((c>>5)<<2)
    int bx = blockIdx.x;
    int tid = threadIdx.x;
    int cur=(t-1)&1, nxt=t&1;
    bool obs = (t < TOBS);
    int tc = obs ? t : (TOBS-1);

    if(bx == 0){
        // ------------- small serial work -------------
        __shared__ float s_pred[NN*2];
        int gate_n_prev = (t>=2) ? d_gateNt[t-1] : 0;
        // phase 1: finalize Ht, zero accumulator
        for(int i=tid;i<NN*EDGE;i+=256){
            if(gate_n_prev) d_Ht[i]=d_Htacc[i];
            d_Htacc[i]=0.f;
        }
        __syncthreads();
        // phase 2: pred_out (!obs): 2 threads per item
        if(!obs){
            int item = tid>>1, sub = tid&1;   // item = n*2+j
            int n = item>>1, j = item&1;
            const float* wp = &W_pred[j*CONC];
            const float* hh = &d_Ht[n*EDGE];
            float acc = 0.f;
            for(int e=sub*64;e<sub*64+64;e++) acc += d_thtT[cur][e*NN+n]*wp[e];
            for(int e=sub*128;e<sub*128+128;e++) acc += hh[e]*wp[NODE+CNN+e];
            acc += __shfl_xor_sync(0xffffffffu, acc, 1);
            if(sub==0) s_pred[item] = acc + d_imgpart[item] + b_pred[j];
        }
        __syncthreads();
        // phase 3: target positions
        if(obs){
            if(tid<NN*2){
                int n=tid>>1, j=tid&1; int off=(n*TOBS+t)*2+j;
                d_cabs[tid]=tabs[off]; d_crel[tid]=trel[off]; d_cstep[tid]=tstep[off];
            }
        }else{
            if(tid<NN*2){
                float p=s_pred[tid];
                d_cabs[tid]+=p;
                float cr=d_crel[tid]+p; d_crel[tid]=cr;
                d_cstep[tid]=p;
                int n=tid>>1, j=tid&1;
                out[(n*PREDN + (t-TOBS))*2 + j] = cr;
            }
        }
        __syncthreads();
        // phase 4: attention weights. 4 threads per n.
        float currNf = d_currNt[t];
        int n = tid>>2, s = tid&3;
        float crel0=d_crel[n*2], crel1=d_crel[n*2+1];
        float p0=0.f,p1=0.f,p2=0.f;
        for(int a=s*16;a<s*16+16;a++){
            float atv = W_att_t[a*2]*crel0 + W_att_t[a*2+1]*crel1 + b_att_t[a];
            p0 += atv*W_att_n[a*2];
            p1 += atv*W_att_n[a*2+1];
            p2 += atv*b_att_n[a];
        }
        #pragma unroll
        for(int o=1;o<4;o<<=1){
            p0 += __shfl_xor_sync(0xffffffffu,p0,o);
            p1 += __shfl_xor_sync(0xffffffffu,p1,o);
            p2 += __shfl_xor_sync(0xffffffffu,p2,o);
        }
        float cab0=d_cabs[n*2], cab1=d_cabs[n*2+1];
        float sc[12], mf[12];
        #pragma unroll
        for(int kk=0;kk<12;kk++){
            int m = n*KK + s*12+kk;
            int off = (m*TOBS+tc)*2;
            float dx=nabs_in[off]-cab0, dy=nabs_in[off+1]-cab1;
            float mv = obs ? ((nhist[m] > (TOBS - t)) ? 1.f : 0.f) : 1.f;
            mf[kk]=mv;
            sc[kk]=(dx*p0+dy*p1+p2)*currNf*0.125f*mv;
        }
        float mx = sc[0];
        #pragma unroll
        for(int kk=1;kk<12;kk++) mx=fmaxf(mx,sc[kk]);
        #pragma unroll
        for(int o=1;o<4;o<<=1) mx = fmaxf(mx, __shfl_xor_sync(0xffffffffu,mx,o));
        float dn = 0.f;
        #pragma unroll
        for(int kk=0;kk<12;kk++) dn += expf(sc[kk]-mx)*mf[kk];
        #pragma unroll
        for(int o=1;o<4;o<<=1) dn += __shfl_xor_sync(0xffffffffu,dn,o);
        dn += 1e-6f;
        #pragma unroll
        for(int kk=0;kk<12;kk++){
            int m = n*KK + s*12+kk;
            d_w[m] = expf(sc[kk]-mx)*mf[kk]/dn;
        }
        // publish
        __threadfence();
        __syncthreads();
        if(tid==0) atomicExch(&d_flag, t);
        return;
    }

    int bi = bx-1;
    int ty = tid>>4, tx = tid&15;
    int pb = tx*8; pb += (pb>>5)<<2;    // physical b col base

    if(bi < 192){
        // ---------- nearby: C(3072x1024), BM=128,BN=128,BK=32, 8x8/thread ----------
        int rowTile = bi%24, colTile = bi/24;
        int m0=rowTile*128, g0=colTile*128, e0=colTile*32;
        const float* A = d_nhtT[cur];       // [k*MM + m]
        ULL accp[8][4];
        #pragma unroll
        for(int i=0;i<8;i++){
            #pragma unroll
            for(int j=0;j<4;j++) accp[i][j]=0ull;
        }
        for(int kt=0; kt<EDGE; kt+=32){
            #pragma unroll
            for(int g=0;g<4;g++){
                int idx = tid + g*256;
                int k = idx>>5, cq = (idx&31)*4;
                *(float4*)&As[k][cq] = *(const float4*)&A[(kt+k)*MM + m0+cq];
                int pc = cq + ((cq>>5)<<2);
                *(float4*)&Bs[k][pc] = *(const float4*)&d_WhhNT[(kt+k)*GN + g0+cq];
            }
            __syncthreads();
            #pragma unroll
            for(int k=0;k<32;k++){
                float4 a0 = *(const float4*)&As[k][ty*8];
                float4 a1 = *(const float4*)&As[k][ty*8+4];
                ulonglong2 bb0 = *(const ulonglong2*)&Bs[k][pb];
                ulonglong2 bb1 = *(const ulonglong2*)&Bs[k][pb+4];
                ULL ap;
                PK(ap,a0.x); FMA2(accp[0][0],ap,bb0.x); FMA2(accp[0][1],ap,bb0.y); FMA2(accp[0][2],ap,bb1.x); FMA2(accp[0][3],ap,bb1.y);
                PK(ap,a0.y); FMA2(accp[1][0],ap,bb0.x); FMA2(accp[1][1],ap,bb0.y); FMA2(accp[1][2],ap,bb1.x); FMA2(accp[1][3],ap,bb1.y);
                PK(ap,a0.z); FMA2(accp[2][0],ap,bb0.x); FMA2(accp[2][1],ap,bb0.y); FMA2(accp[2][2],ap,bb1.x); FMA2(accp[2][3],ap,bb1.y);
                PK(ap,a0.w); FMA2(accp[3][0],ap,bb0.x); FMA2(accp[3][1],ap,bb0.y); FMA2(accp[3][2],ap,bb1.x); FMA2(accp[3][3],ap,bb1.y);
                PK(ap,a1.x); FMA2(accp[4][0],ap,bb0.x); FMA2(accp[4][1],ap,bb0.y); FMA2(accp[4][2],ap,bb1.x); FMA2(accp[4][3],ap,bb1.y);
                PK(ap,a1.y); FMA2(accp[5][0],ap,bb0.x); FMA2(accp[5][1],ap,bb0.y); FMA2(accp[5][2],ap,bb1.x); FMA2(accp[5][3],ap,bb1.y);
                PK(ap,a1.z); FMA2(accp[6][0],ap,bb0.x); FMA2(accp[6][1],ap,bb0.y); FMA2(accp[6][2],ap,bb1.x); FMA2(accp[6][3],ap,bb1.y);
                PK(ap,a1.w); FMA2(accp[7][0],ap,bb0.x); FMA2(accp[7][1],ap,bb0.y); FMA2(accp[7][2],ap,bb1.x); FMA2(accp[7][3],ap,bb1.y);
            }
            __syncthreads();
        }
        // wait for small work
        if(tid==0){ while(atomicAdd(&d_flag,0) < t){} }
        __syncthreads();
        __threadfence();
        int gate_n = d_gateNt[t];
        #pragma unroll
        for(int i=0;i<8;i++){
            int m = m0 + ty*8 + i;
            int off = (m*TOBS+tc)*2;
            float x0=nstep_in[off], x1=nstep_in[off+1];
            bool mv = obs ? (nhist[m] > (TOBS - t)) : true;
            float wv = d_w[m];
            int hn = (m/KK)*EDGE;
            #pragma unroll
            for(int c=0;c<2;c++){
                float g4[4];
                UPK(g4[0],g4[1],accp[i][c*2]);
                UPK(g4[2],g4[3],accp[i][c*2+1]);
                int rr = g0 + tx*8 + c*4;
                #pragma unroll
                for(int q=0;q<4;q++)
                    g4[q] += x0*d_WxN[(rr+q)*2] + x1*d_WxN[(rr+q)*2+1] + d_bN[rr+q];
                float ig=sigm(g4[0]), fg=sigm(g4[1]), gg=tanhf(g4[2]), og=sigm(g4[3]);
                int e = e0 + tx*2 + c;
                float cold = d_nct[m*EDGE+e];
                float c2 = fg*cold + ig*gg;
                float h2 = og*tanhf(c2);
                bool un = gate_n && mv;
                float hv;
                if(un){ d_nct[m*EDGE+e]=c2; hv=h2; }
                else  { hv = d_nhtT[cur][e*MM+m]; }
                d_nhtT[nxt][e*MM+m]=hv;
                if(gate_n && wv!=0.f) atomicAdd(&d_Htacc[hn+e], wv*hv);
            }
        }
    }else{
        // ---------- target: C(64x512), BM=64,BN=128,BK=32, 4x8/thread ----------
        int bj = bi-192;
        int g0 = bj*128, e0 = bj*32;
        const float* A = d_thtT[cur];       // [k*NN + n]
        ULL accp[4][4];
        #pragma unroll
        for(int i=0;i<4;i++){
            #pragma unroll
            for(int j=0;j<4;j++) accp[i][j]=0ull;
        }
        for(int kt=0; kt<NODE; kt+=32){
            #pragma unroll
            for(int g=0;g<2;g++){
                int idx = tid + g*256;
                int k = idx>>4, nq = (idx&15)*4;
                *(float4*)&As[k][nq] = *(const float4*)&A[(kt+k)*NN + nq];
            }
            #pragma unroll
            for(int g=0;g<4;g++){
                int idx = tid + g*256;
                int k = idx>>5, cq = (idx&31)*4;
                int pc = cq + ((cq>>5)<<2);
                *(float4*)&Bs[k][pc] = *(const float4*)&d_WhhTT[(kt+k)*GT + g0+cq];
            }
            __syncthreads();
            #pragma unroll
            for(int k=0;k<32;k++){
                float4 a0 = *(const float4*)&As[k][ty*4];
                ulonglong2 bb0 = *(const ulonglong2*)&Bs[k][pb];
                ulonglong2 bb1 = *(const ulonglong2*)&Bs[k][pb+4];
                ULL ap;
                PK(ap,a0.x); FMA2(accp[0][0],ap,bb0.x); FMA2(accp[0][1],ap,bb0.y); FMA2(accp[0][2],ap,bb1.x); FMA2(accp[0][3],ap,bb1.y);
                PK(ap,a0.y); FMA2(accp[1][0],ap,bb0.x); FMA2(accp[1][1],ap,bb0.y); FMA2(accp[1][2],ap,bb1.x); FMA2(accp[1][3],ap,bb1.y);
                PK(ap,a0.z); FMA2(accp[2][0],ap,bb0.x); FMA2(accp[2][1],ap,bb0.y); FMA2(accp[2][2],ap,bb1.x); FMA2(accp[2][3],ap,bb1.y);
                PK(ap,a0.w); FMA2(accp[3][0],ap,bb0.x); FMA2(accp[3][1],ap,bb0.y); FMA2(accp[3][2],ap,bb1.x); FMA2(accp[3][3],ap,bb1.y);
            }
            __syncthreads();
        }
        if(tid==0){ while(atomicAdd(&d_flag,0) < t){} }
        __syncthreads();
        __threadfence();
        int gate_t = d_gateTt[t];
        #pragma unroll
        for(int i=0;i<4;i++){
            int n = ty*4 + i;
            float x0=d_cstep[n*2], x1=d_cstep[n*2+1];
            bool tm = obs ? (thist[n] > (TOBS - t)) : true;
            #pragma unroll
            for(int c=0;c<2;c++){
                float g4[4];
                UPK(g4[0],g4[1],accp[i][c*2]);
                UPK(g4[2],g4[3],accp[i][c*2+1]);
                int rr = g0 + tx*8 + c*4;
                #pragma unroll
                for(int q=0;q<4;q++)
                    g4[q] += x0*d_WxT[(rr+q)*2] + x1*d_WxT[(rr+q)*2+1] + d_bT[rr+q];
                float ig=sigm(g4[0]), fg=sigm(g4[1]), gg=tanhf(g4[2]), og=sigm(g4[3]);
                int e = e0 + tx*2 + c;
                float cold = d_tct[n*NODE+e];
                float c2 = fg*cold + ig*gg;
                float h2 = og*tanhf(c2);
                bool un = gate_t && tm;
                float hv;
                if(un){ d_tct[n*NODE+e]=c2; hv=h2; }
                else  { hv = d_thtT[cur][e*NN+n]; }
                d_thtT[nxt][e*NN+n]=hv;
            }
        }
    }
}

// ---------------- launch ----------------
extern "C" void kernel_launch(void* const* d_in, const int* in_sizes, int n_in,
                              void* d_out, int out_size)
{
    const float* img    = (const float*)d_in[0];
    const float* tabs   = (const float*)d_in[1];
    const float* trel   = (const float*)d_in[2];
    const float* tstep  = (const float*)d_in[3];
    const float* nabs   = (const float*)d_in[4];
    // d_in[5] = nearby_obs_pos_rel (unused by reference step)
    const float* nstep  = (const float*)d_in[6];
    const int*   thist  = (const int*)d_in[7];
    const int*   nhist  = (const int*)d_in[8];
    const float* W_disp = (const float*)d_in[9];
    const float* b_disp = (const float*)d_in[10];
    const float* Wih_t  = (const float*)d_in[11];
    const float* Whh_t  = (const float*)d_in[12];
    const float* bih_t  = (const float*)d_in[13];
    const float* bhh_t  = (const float*)d_in[14];
    const float* Wih_n  = (const float*)d_in[15];
    const float* Whh_n  = (const float*)d_in[16];
    const float* bih_n  = (const float*)d_in[17];
    const float* bhh_n  = (const float*)d_in[18];
    const float* W_att_t= (const float*)d_in[19];
    const float* b_att_t= (const float*)d_in[20];
    const float* W_att_n= (const float*)d_in[21];
    const float* b_att_n= (const float*)d_in[22];
    const float* W_pred = (const float*)d_in[23];
    const float* b_pred = (const float*)d_in[24];
    float* out = (float*)d_out;

    k_zero<<<256,256>>>();
    k_tables<<<TSTEPS-1,256>>>(thist,nhist);
    k_prep<<<256,256>>>(Whh_n,Wih_n,bih_n,bhh_n,Whh_t,Wih_t,bih_t,bhh_t,
                        W_disp,b_disp,img,W_pred);
    for(int t=1; t<TSTEPS; t++){
        k_step<<<197,256>>>(t,tabs,trel,tstep,nabs,nstep,thist,nhist,
                            W_att_t,b_att_t,W_att_n,b_att_n,W_pred,b_pred,out);
    }
}

// round 4
// speedup vs baseline: 1.8603x; 1.1192x over previous
#include <cuda_runtime.h>
#include <math.h>

#define NN    64
#define KK    48
#define MM    (NN*KK)      // 3072
#define TOBS  30
#define PREDN 15
#define TSTEPS (TOBS+PREDN)  // 45, t runs 1..44
#define EMB   64
#define NODE  128
#define EDGE  256
#define ATTD  64
#define CNN   512
#define GT    (4*NODE)     // 512
#define GN    (4*EDGE)     // 1024
#define CONC  (NODE+CNN+EDGE) // 896

typedef unsigned long long ULL;

// f32x2 packed math (bitwise == 2x scalar fp32 fma)
#define PK(d,s)   asm("mov.b64 %0, {%1, %1};" : "=l"(d) : "f"(s))
#define UPK(lo,hi,p) asm("mov.b64 {%0, %1}, %2;" : "=f"(lo), "=f"(hi) : "l"(p))
#define FMA2(c,a,b) asm("fma.rn.f32x2 %0, %1, %2, %0;" : "+l"(c) : "l"(a), "l"(b))

// ---------------- persistent device state ----------------
// transposed layouts: nhtT[e][m], thtT[e][n]
__device__ float d_thtT[2][NODE*NN];
__device__ float d_tct[NN*NODE];
__device__ float d_nhtT[2][EDGE*MM];
__device__ float d_nct[MM*EDGE];
__device__ float d_Ht[NN*EDGE];
__device__ float d_Htacc[NN*EDGE];
__device__ float d_cabs[NN*2], d_crel[NN*2], d_cstep[NN*2];
__device__ float d_w[MM];      // attention weights
__device__ int   d_flag;       // step publish flag
// per-step gate tables
__device__ int   d_gateTt[TSTEPS];
__device__ int   d_gateNt[TSTEPS];
__device__ float d_currNt[TSTEPS];
// preprocessed weights, transposed + gate-interleaved: col g = e*4+q
__device__ float d_WhhNT[EDGE*GN];   // [k][g]
__device__ float d_WhhTT[NODE*GT];   // [k][g]
__device__ float d_WxN[GN*2], d_bN[GN];
__device__ float d_WxT[GT*2], d_bT[GT];
__device__ float d_imgpart[NN*2];

__device__ __forceinline__ float sigm(float x){ return 1.f/(1.f+expf(-x)); }

// ---------------- init: zero state ----------------
__global__ void k_zero(){
    long i0 = (long)blockIdx.x*blockDim.x + threadIdx.x;
    long st = (long)gridDim.x*blockDim.x;
    float* nh = &d_nhtT[0][0];
    for(long i=i0;i<2L*MM*EDGE;i+=st) nh[i]=0.f;
    for(long i=i0;i<(long)MM*EDGE;i+=st) d_nct[i]=0.f;
    float* th = &d_thtT[0][0];
    for(long i=i0;i<2L*NN*NODE;i+=st) th[i]=0.f;
    for(long i=i0;i<(long)NN*NODE;i+=st) d_tct[i]=0.f;
    for(long i=i0;i<(long)NN*EDGE;i+=st){ d_Ht[i]=0.f; d_Htacc[i]=0.f; }
    if(i0<NN*2){ d_cabs[i0]=0.f; d_crel[i0]=0.f; d_cstep[i0]=0.f; }
    if(i0==0) d_flag=0;
}

// ---------------- init: per-step gate tables ----------------
__global__ void k_tables(const int* __restrict__ thist, const int* __restrict__ nhist){
    int t = blockIdx.x + 1;             // 1..44
    int tid = threadIdx.x;
    __shared__ int s_cnt[256];
    __shared__ int s_any[256];
    int cnt=0, any=0;
    if(t < TOBS){
        for(int m=tid;m<MM;m+=256) cnt += (nhist[m] > (TOBS - t)) ? 1 : 0;
        for(int n=tid;n<NN;n+=256) any |= (thist[n] > (TOBS - t)) ? 1 : 0;
    }else{
        cnt = (tid==0)?MM:0; any = 1;
    }
    s_cnt[tid]=cnt; s_any[tid]=any;
    __syncthreads();
    for(int o=128;o>0;o>>=1){
        if(tid<o){ s_cnt[tid]+=s_cnt[tid+o]; s_any[tid]|=s_any[tid+o]; }
        __syncthreads();
    }
    if(tid==0){
        int gt = s_any[0]?1:0;
        int cn = s_cnt[0];
        int gn = (gt && cn>0)?1:0;
        d_gateTt[t]=gt; d_gateNt[t]=gn; d_currNt[t]=(float)cn;
    }
}

// ---------------- init: preprocess weights ----------------
__global__ void k_prep(const float* __restrict__ Whh_n, const float* __restrict__ Wih_n,
                       const float* __restrict__ bih_n, const float* __restrict__ bhh_n,
                       const float* __restrict__ Whh_t, const float* __restrict__ Wih_t,
                       const float* __restrict__ bih_t, const float* __restrict__ bhh_t,
                       const float* __restrict__ W_disp, const float* __restrict__ b_disp,
                       const float* __restrict__ img, const float* __restrict__ W_pred){
    int i0 = blockIdx.x*blockDim.x + threadIdx.x;
    int st = gridDim.x*blockDim.x;
    // transposed + gate-interleaved: d_WhhNT[k*GN + g], g=e*4+q
    for(int i=i0;i<EDGE*GN;i+=st){
        int k=i/GN, g=i%GN; int e=g>>2, q=g&3;
        d_WhhNT[i] = Whh_n[(q*EDGE+e)*EDGE + k];
    }
    for(int i=i0;i<NODE*GT;i+=st){
        int k=i/GT, g=i%GT; int e=g>>2, q=g&3;
        d_WhhTT[i] = Whh_t[(q*NODE+e)*NODE + k];
    }
    for(int r=i0;r<GN;r+=st){
        int e=r>>2, q=r&3; int o=q*EDGE+e;
        float w0=0.f,w1=0.f,bb=bih_n[o]+bhh_n[o];
        for(int d=0;d<EMB;d++){
            float wi=Wih_n[o*EMB+d];
            w0+=wi*W_disp[d*2]; w1+=wi*W_disp[d*2+1]; bb+=wi*b_disp[d];
        }
        d_WxN[r*2]=w0; d_WxN[r*2+1]=w1; d_bN[r]=bb;
    }
    for(int r=i0;r<GT;r+=st){
        int e=r>>2, q=r&3; int o=q*NODE+e;
        float w0=0.f,w1=0.f,bb=bih_t[o]+bhh_t[o];
        for(int d=0;d<EMB;d++){
            float wi=Wih_t[o*EMB+d];
            w0+=wi*W_disp[d*2]; w1+=wi*W_disp[d*2+1]; bb+=wi*b_disp[d];
        }
        d_WxT[r*2]=w0; d_WxT[r*2+1]=w1; d_bT[r]=bb;
    }
    for(int i=i0;i<NN*2;i+=st){
        int n=i>>1, j=i&1; float s=0.f;
        for(int c=0;c<CNN;c++) s += img[n*CNN+c]*W_pred[j*CONC + NODE + c];
        d_imgpart[i]=s;
    }
}

// =========================================================================
// per-step kernel: block 0 = small serial work, publishes d_flag=t.
// blocks 1..384: nearby GEMM+LSTM (BM=64,BN=128). blocks 385..388: target.
// 3 CTAs/SM resident -> whole grid is one wave; latency hidden by 24 warps/SM.
// =========================================================================
__global__ void __launch_bounds__(256,3) k_step(int t,
    const float* __restrict__ tabs, const float* __restrict__ trel, const float* __restrict__ tstep,
    const float* __restrict__ nabs_in, const float* __restrict__ nstep_in,
    const int* __restrict__ thist, const int* __restrict__ nhist,
    const float* __restrict__ W_att_t, const float* __restrict__ b_att_t,
    const float* __restrict__ W_att_n, const float* __restrict__ b_att_n,
    const float* __restrict__ W_pred, const float* __restrict__ b_pred,
    float* __restrict__ out)
{
    __shared__ __align__(16) float As[32][68];    // 64 cols + pad
    __shared__ __align__(16) float Bs[32][140];   // physical col p(c)=c+((c>>5)<<2)
    int bx = blockIdx.x;
    int tid = threadIdx.x;
    int cur=(t-1)&1, nxt=t&1;
    bool obs = (t < TOBS);
    int tc = obs ? t : (TOBS-1);

    if(bx == 0){
        // ------------- small serial work -------------
        __shared__ float s_pred[NN*2];
        int gate_n_prev = (t>=2) ? d_gateNt[t-1] : 0;
        for(int i=tid;i<NN*EDGE;i+=256){
            if(gate_n_prev) d_Ht[i]=d_Htacc[i];
            d_Htacc[i]=0.f;
        }
        __syncthreads();
        if(!obs){
            int item = tid>>1, sub = tid&1;   // item = n*2+j
            int n = item>>1, j = item&1;
            const float* wp = &W_pred[j*CONC];
            const float* hh = &d_Ht[n*EDGE];
            float acc = 0.f;
            for(int e=sub*64;e<sub*64+64;e++) acc += d_thtT[cur][e*NN+n]*wp[e];
            for(int e=sub*128;e<sub*128+128;e++) acc += hh[e]*wp[NODE+CNN+e];
            acc += __shfl_xor_sync(0xffffffffu, acc, 1);
            if(sub==0) s_pred[item] = acc + d_imgpart[item] + b_pred[j];
        }
        __syncthreads();
        if(obs){
            if(tid<NN*2){
                int n=tid>>1, j=tid&1; int off=(n*TOBS+t)*2+j;
                d_cabs[tid]=tabs[off]; d_crel[tid]=trel[off]; d_cstep[tid]=tstep[off];
            }
        }else{
            if(tid<NN*2){
                float p=s_pred[tid];
                d_cabs[tid]+=p;
                float cr=d_crel[tid]+p; d_crel[tid]=cr;
                d_cstep[tid]=p;
                int n=tid>>1, j=tid&1;
                out[(n*PREDN + (t-TOBS))*2 + j] = cr;
            }
        }
        __syncthreads();
        // attention weights. 4 threads per n.
        float currNf = d_currNt[t];
        int n = tid>>2, s = tid&3;
        float crel0=d_crel[n*2], crel1=d_crel[n*2+1];
        float p0=0.f,p1=0.f,p2=0.f;
        for(int a=s*16;a<s*16+16;a++){
            float atv = W_att_t[a*2]*crel0 + W_att_t[a*2+1]*crel1 + b_att_t[a];
            p0 += atv*W_att_n[a*2];
            p1 += atv*W_att_n[a*2+1];
            p2 += atv*b_att_n[a];
        }
        #pragma unroll
        for(int o=1;o<4;o<<=1){
            p0 += __shfl_xor_sync(0xffffffffu,p0,o);
            p1 += __shfl_xor_sync(0xffffffffu,p1,o);
            p2 += __shfl_xor_sync(0xffffffffu,p2,o);
        }
        float cab0=d_cabs[n*2], cab1=d_cabs[n*2+1];
        float sc[12], mf[12];
        #pragma unroll
        for(int kk=0;kk<12;kk++){
            int m = n*KK + s*12+kk;
            int off = (m*TOBS+tc)*2;
            float dx=nabs_in[off]-cab0, dy=nabs_in[off+1]-cab1;
            float mv = obs ? ((nhist[m] > (TOBS - t)) ? 1.f : 0.f) : 1.f;
            mf[kk]=mv;
            sc[kk]=(dx*p0+dy*p1+p2)*currNf*0.125f*mv;
        }
        float mx = sc[0];
        #pragma unroll
        for(int kk=1;kk<12;kk++) mx=fmaxf(mx,sc[kk]);
        #pragma unroll
        for(int o=1;o<4;o<<=1) mx = fmaxf(mx, __shfl_xor_sync(0xffffffffu,mx,o));
        float dn = 0.f;
        #pragma unroll
        for(int kk=0;kk<12;kk++) dn += expf(sc[kk]-mx)*mf[kk];
        #pragma unroll
        for(int o=1;o<4;o<<=1) dn += __shfl_xor_sync(0xffffffffu,dn,o);
        dn += 1e-6f;
        #pragma unroll
        for(int kk=0;kk<12;kk++){
            int m = n*KK + s*12+kk;
            d_w[m] = expf(sc[kk]-mx)*mf[kk]/dn;
        }
        __threadfence();
        __syncthreads();
        if(tid==0) atomicExch(&d_flag, t);
        return;
    }

    int bi = bx-1;
    int ty = tid>>4, tx = tid&15;
    int pb = tx*8; pb += (pb>>5)<<2;    // physical b col base
    ULL accp[4][4];
    #pragma unroll
    for(int i=0;i<4;i++){
        #pragma unroll
        for(int j=0;j<4;j++) accp[i][j]=0ull;
    }

    if(bi < 384){
        // ---------- nearby: C(3072x1024), BM=64,BN=128,BK=32, 4x8/thread ----------
        int rowTile = bi%48, colTile = bi/48;
        int m0=rowTile*64, g0=colTile*128, e0=colTile*32;
        const float* A = d_nhtT[cur];       // [k*MM + m]
        for(int kt=0; kt<EDGE; kt+=32){
            #pragma unroll
            for(int g=0;g<2;g++){
                int idx = tid + g*256;
                int k = idx>>4, mq = (idx&15)*4;
                *(float4*)&As[k][mq] = *(const float4*)&A[(kt+k)*MM + m0+mq];
            }
            #pragma unroll
            for(int g=0;g<4;g++){
                int idx = tid + g*256;
                int k = idx>>5, cq = (idx&31)*4;
                int pc = cq + ((cq>>5)<<2);
                *(float4*)&Bs[k][pc] = *(const float4*)&d_WhhNT[(kt+k)*GN + g0+cq];
            }
            __syncthreads();
            #pragma unroll
            for(int k=0;k<32;k++){
                float4 a0 = *(const float4*)&As[k][ty*4];
                ulonglong2 bb0 = *(const ulonglong2*)&Bs[k][pb];
                ulonglong2 bb1 = *(const ulonglong2*)&Bs[k][pb+4];
                ULL ap;
                PK(ap,a0.x); FMA2(accp[0][0],ap,bb0.x); FMA2(accp[0][1],ap,bb0.y); FMA2(accp[0][2],ap,bb1.x); FMA2(accp[0][3],ap,bb1.y);
                PK(ap,a0.y); FMA2(accp[1][0],ap,bb0.x); FMA2(accp[1][1],ap,bb0.y); FMA2(accp[1][2],ap,bb1.x); FMA2(accp[1][3],ap,bb1.y);
                PK(ap,a0.z); FMA2(accp[2][0],ap,bb0.x); FMA2(accp[2][1],ap,bb0.y); FMA2(accp[2][2],ap,bb1.x); FMA2(accp[2][3],ap,bb1.y);
                PK(ap,a0.w); FMA2(accp[3][0],ap,bb0.x); FMA2(accp[3][1],ap,bb0.y); FMA2(accp[3][2],ap,bb1.x); FMA2(accp[3][3],ap,bb1.y);
            }
            __syncthreads();
        }
        // wait for small work
        if(tid==0){ while(atomicAdd(&d_flag,0) < t){} }
        __syncthreads();
        __threadfence();
        int gate_n = d_gateNt[t];
        #pragma unroll
        for(int i=0;i<4;i++){
            int m = m0 + ty*4 + i;
            int off = (m*TOBS+tc)*2;
            float x0=nstep_in[off], x1=nstep_in[off+1];
            bool mv = obs ? (nhist[m] > (TOBS - t)) : true;
            float wv = d_w[m];
            int hn = (m/KK)*EDGE;
            #pragma unroll
            for(int c=0;c<2;c++){
                float g4[4];
                UPK(g4[0],g4[1],accp[i][c*2]);
                UPK(g4[2],g4[3],accp[i][c*2+1]);
                int rr = g0 + tx*8 + c*4;
                #pragma unroll
                for(int q=0;q<4;q++)
                    g4[q] += x0*d_WxN[(rr+q)*2] + x1*d_WxN[(rr+q)*2+1] + d_bN[rr+q];
                float ig=sigm(g4[0]), fg=sigm(g4[1]), gg=tanhf(g4[2]), og=sigm(g4[3]);
                int e = e0 + tx*2 + c;
                float cold = d_nct[m*EDGE+e];
                float c2 = fg*cold + ig*gg;
                float h2 = og*tanhf(c2);
                bool un = gate_n && mv;
                float hv;
                if(un){ d_nct[m*EDGE+e]=c2; hv=h2; }
                else  { hv = d_nhtT[cur][e*MM+m]; }
                d_nhtT[nxt][e*MM+m]=hv;
                if(gate_n && wv!=0.f) atomicAdd(&d_Htacc[hn+e], wv*hv);
            }
        }
    }else{
        // ---------- target: C(64x512), BM=64,BN=128,BK=32, 4x8/thread ----------
        int bj = bi-384;
        int g0 = bj*128, e0 = bj*32;
        const float* A = d_thtT[cur];       // [k*NN + n]
        for(int kt=0; kt<NODE; kt+=32){
            #pragma unroll
            for(int g=0;g<2;g++){
                int idx = tid + g*256;
                int k = idx>>4, nq = (idx&15)*4;
                *(float4*)&As[k][nq] = *(const float4*)&A[(kt+k)*NN + nq];
            }
            #pragma unroll
            for(int g=0;g<4;g++){
                int idx = tid + g*256;
                int k = idx>>5, cq = (idx&31)*4;
                int pc = cq + ((cq>>5)<<2);
                *(float4*)&Bs[k][pc] = *(const float4*)&d_WhhTT[(kt+k)*GT + g0+cq];
            }
            __syncthreads();
            #pragma unroll
            for(int k=0;k<32;k++){
                float4 a0 = *(const float4*)&As[k][ty*4];
                ulonglong2 bb0 = *(const ulonglong2*)&Bs[k][pb];
                ulonglong2 bb1 = *(const ulonglong2*)&Bs[k][pb+4];
                ULL ap;
                PK(ap,a0.x); FMA2(accp[0][0],ap,bb0.x); FMA2(accp[0][1],ap,bb0.y); FMA2(accp[0][2],ap,bb1.x); FMA2(accp[0][3],ap,bb1.y);
                PK(ap,a0.y); FMA2(accp[1][0],ap,bb0.x); FMA2(accp[1][1],ap,bb0.y); FMA2(accp[1][2],ap,bb1.x); FMA2(accp[1][3],ap,bb1.y);
                PK(ap,a0.z); FMA2(accp[2][0],ap,bb0.x); FMA2(accp[2][1],ap,bb0.y); FMA2(accp[2][2],ap,bb1.x); FMA2(accp[2][3],ap,bb1.y);
                PK(ap,a0.w); FMA2(accp[3][0],ap,bb0.x); FMA2(accp[3][1],ap,bb0.y); FMA2(accp[3][2],ap,bb1.x); FMA2(accp[3][3],ap,bb1.y);
            }
            __syncthreads();
        }
        if(tid==0){ while(atomicAdd(&d_flag,0) < t){} }
        __syncthreads();
        __threadfence();
        int gate_t = d_gateTt[t];
        #pragma unroll
        for(int i=0;i<4;i++){
            int n = ty*4 + i;
            float x0=d_cstep[n*2], x1=d_cstep[n*2+1];
            bool tm = obs ? (thist[n] > (TOBS - t)) : true;
            #pragma unroll
            for(int c=0;c<2;c++){
                float g4[4];
                UPK(g4[0],g4[1],accp[i][c*2]);
                UPK(g4[2],g4[3],accp[i][c*2+1]);
                int rr = g0 + tx*8 + c*4;
                #pragma unroll
                for(int q=0;q<4;q++)
                    g4[q] += x0*d_WxT[(rr+q)*2] + x1*d_WxT[(rr+q)*2+1] + d_bT[rr+q];
                float ig=sigm(g4[0]), fg=sigm(g4[1]), gg=tanhf(g4[2]), og=sigm(g4[3]);
                int e = e0 + tx*2 + c;
                float cold = d_tct[n*NODE+e];
                float c2 = fg*cold + ig*gg;
                float h2 = og*tanhf(c2);
                bool un = gate_t && tm;
                float hv;
                if(un){ d_tct[n*NODE+e]=c2; hv=h2; }
                else  { hv = d_thtT[cur][e*NN+n]; }
                d_thtT[nxt][e*NN+n]=hv;
            }
        }
    }
}

// ---------------- launch ----------------
extern "C" void kernel_launch(void* const* d_in, const int* in_sizes, int n_in,
                              void* d_out, int out_size)
{
    const float* img    = (const float*)d_in[0];
    const float* tabs   = (const float*)d_in[1];
    const float* trel   = (const float*)d_in[2];
    const float* tstep  = (const float*)d_in[3];
    const float* nabs   = (const float*)d_in[4];
    // d_in[5] = nearby_obs_pos_rel (unused by reference step)
    const float* nstep  = (const float*)d_in[6];
    const int*   thist  = (const int*)d_in[7];
    const int*   nhist  = (const int*)d_in[8];
    const float* W_disp = (const float*)d_in[9];
    const float* b_disp = (const float*)d_in[10];
    const float* Wih_t  = (const float*)d_in[11];
    const float* Whh_t  = (const float*)d_in[12];
    const float* bih_t  = (const float*)d_in[13];
    const float* bhh_t  = (const float*)d_in[14];
    const float* Wih_n  = (const float*)d_in[15];
    const float* Whh_n  = (const float*)d_in[16];
    const float* bih_n  = (const float*)d_in[17];
    const float* bhh_n  = (const float*)d_in[18];
    const float* W_att_t= (const float*)d_in[19];
    const float* b_att_t= (const float*)d_in[20];
    const float* W_att_n= (const float*)d_in[21];
    const float* b_att_n= (const float*)d_in[22];
    const float* W_pred = (const float*)d_in[23];
    const float* b_pred = (const float*)d_in[24];
    float* out = (float*)d_out;

    k_zero<<<256,256>>>();
    k_tables<<<TSTEPS-1,256>>>(thist,nhist);
    k_prep<<<256,256>>>(Whh_n,Wih_n,bih_n,bhh_n,Whh_t,Wih_t,bih_t,bhh_t,
                        W_disp,b_disp,img,W_pred);
    for(int t=1; t<TSTEPS; t++){
        k_step<<<389,256>>>(t,tabs,trel,tstep,nabs,nstep,thist,nhist,
                            W_att_t,b_att_t,W_att_n,b_att_n,W_pred,b_pred,out);
    }
}